// round 11
// baseline (speedup 1.0000x reference)
#include <cuda_runtime.h>
#include <math.h>

#define BATCH 16
#define NPTS  2048
#define KNN   10

__device__ float4 g_s4[BATCH * NPTS];   // x, y, z, |p|^2
__device__ float4 g_t4[BATCH * NPTS];   // tx, ty, tz, 0
__device__ float g_loss[BATCH * NPTS];
__device__ unsigned int g_min[BATCH];   // float bits; positive => int-min == float-min
__device__ int g_qcnt[BATCH * NPTS * 4];         // per-quarter hit counts
__device__ int g_qidx[BATCH * NPTS * 4 * KNN];   // per-quarter ascending index lists

// Packed f32x2 helpers (per-lane IEEE fp32, identical rounding to scalar ops)
#define PACK2(out, lo, hi)  asm("mov.b64 %0, {%1, %2};" : "=l"(out) : "f"(lo), "f"(hi))
#define UNPACK2(lo, hi, in) asm("mov.b64 {%0, %1}, %2;" : "=f"(lo), "=f"(hi) : "l"(in))
#define MUL2(out, a, b)     asm("mul.rn.f32x2 %0, %1, %2;" : "=l"(out) : "l"(a), "l"(b))
#define ADD2(out, a, b)     asm("add.rn.f32x2 %0, %1, %2;" : "=l"(out) : "l"(a), "l"(b))
#define FMA2(out, a, b, c)  asm("fma.rn.f32x2 %0, %1, %2, %3;" : "=l"(out) : "l"(a), "l"(b), "l"(c))

typedef unsigned long long u64;

__device__ __forceinline__ void sort3(float& a, float& b, float& c) {
    float lo = fminf(a, b), hi = fmaxf(a, b);
    float l0 = fminf(lo, c);
    float l2 = fmaxf(hi, c);
    float l1 = fmaxf(lo, fminf(hi, c));
    a = l0; b = l1; c = l2;
}

// keys for candidate pair (2u, 2u+1): key = ((sqn + sq_m) - 2*dot) + 1e-7,
// dot = x*cx fma y*cy fma z*cz — identical rounding to the verified scalar.
__device__ __forceinline__ void keys2(const float4 xy, const float4 zw,
                                      u64 xn2, u64 yn2, u64 zn2, u64 sqn2,
                                      u64 neg2, u64 eps2,
                                      float& k0, float& k1) {
    u64 cx2, cy2, cz2, cw2, t, s, d, k;
    PACK2(cx2, xy.x, xy.y); PACK2(cy2, xy.z, xy.w);
    PACK2(cz2, zw.x, zw.y); PACK2(cw2, zw.z, zw.w);
    MUL2(t, xn2, cx2);
    FMA2(t, yn2, cy2, t);
    FMA2(t, zn2, cz2, t);          // dot
    ADD2(s, sqn2, cw2);            // sqn + sq_m
    FMA2(d, t, neg2, s);           // d2 = s - 2*dot (one rounding, == scalar)
    ADD2(k, d, eps2);              // key = d2 + 1e-7
    UNPACK2(k0, k1, k);
}

// prep: transpose + squared norms into float4 arrays; also init g_min.
__global__ __launch_bounds__(256) void prep_kernel(const float* __restrict__ src,
                                                   const float* __restrict__ tgt) {
    const int b     = blockIdx.x >> 3;
    const int chunk = blockIdx.x & 7;
    const int tid   = threadIdx.x;
    if (blockIdx.x == 0 && tid < BATCH) g_min[tid] = 0x7f800000u;  // +inf
    const float* sb = src + b * 3 * NPTS;
    const float* tb = tgt + b * 3 * NPTS;
    const int i = chunk * 256 + tid;
    float x = sb[i], y = sb[NPTS + i], z = sb[2 * NPTS + i];
    g_s4[b * NPTS + i] = make_float4(x, y, z, x * x + y * y + z * z);
    g_t4[b * NPTS + i] = make_float4(tb[i], tb[NPTS + i], tb[2 * NPTS + i], 0.0f);
}

// Dynamic smem for knn_kernel (register-light: phases 1-2 only)
#define SM_PXY   0                        // 1024 float4 (16 KB)
#define SM_PZW   16384                    // 1024 float4 (16 KB)
#define SM_FBUF  32768                    // 3*256*10 float (30 KB) quarter value lists
#define SM_THR   63488                    // 256 float (1 KB)
#define SM_TOTAL 64512

__global__ __launch_bounds__(1024) void knn_kernel() {
    extern __shared__ unsigned char smem[];
    float4* pxy  = (float4*)(smem + SM_PXY);   // (x0,x1,y0,y1) per candidate pair
    float4* pzw  = (float4*)(smem + SM_PZW);   // (z0,z1,sq0,sq1)
    float*  fbuf = (float*)(smem + SM_FBUF);
    float*  sthr = (float*)(smem + SM_THR);

    const int b     = blockIdx.x >> 3;
    const int chunk = blockIdx.x & 7;
    const int tid   = threadIdx.x;
    const int q     = tid & 255;          // query slot within chunk
    const int qt    = tid >> 8;           // quarter: candidates [qt*512, qt*512+512)
    const int n     = chunk * 256 + q;

    const float4* s4b = g_s4 + b * NPTS;
    {   // 1024 threads load 1024 candidate pairs: one each
        const int i = tid;
        float4 a = s4b[2 * i], c = s4b[2 * i + 1];
        pxy[i] = make_float4(a.x, c.x, a.y, c.y);
        pzw[i] = make_float4(a.z, c.z, a.w, c.w);
    }
    __syncthreads();

    const float FINF = __int_as_float(0x7f800000);

    const float4 pn = s4b[n];
    u64 xn2, yn2, zn2, sqn2, neg2, eps2;
    PACK2(xn2, pn.x, pn.x); PACK2(yn2, pn.y, pn.y);
    PACK2(zn2, pn.z, pn.z); PACK2(sqn2, pn.w, pn.w);
    { float m2 = -2.0f, ep = 1e-7f; PACK2(neg2, m2, m2); PACK2(eps2, ep, ep); }

    const int mlo = qt * (NPTS / 4);
    const int mhi = mlo + NPTS / 4;

    // ---- Pass 1 (per quarter): 10 smallest masked keys via min-max lattice.
    // Mask (key < 0.1 -> +inf) as a select; batch min-tree screens 8 at once.
    // Insert set identical to (key < th && key >= 0.1): inf never < th.
    float kb[KNN];
#pragma unroll
    for (int i = 0; i < KNN; i++) kb[i] = FINF;
    float th = FINF;

    for (int m0 = mlo; m0 < mhi; m0 += 8) {
        float cm[8];
#pragma unroll
        for (int up = 0; up < 4; up++) {
            float k0, k1;
            keys2(pxy[(m0 >> 1) + up], pzw[(m0 >> 1) + up],
                  xn2, yn2, zn2, sqn2, neg2, eps2, k0, k1);
            cm[2 * up]     = (k0 >= 0.1f) ? k0 : FINF;
            cm[2 * up + 1] = (k1 >= 0.1f) ? k1 : FINF;
        }
        float b0 = fminf(fminf(cm[0], cm[1]), fminf(cm[2], cm[3]));
        float b1 = fminf(fminf(cm[4], cm[5]), fminf(cm[6], cm[7]));
        if (fminf(b0, b1) < th) {
#pragma unroll
            for (int u = 0; u < 8; u++) {
                float c = cm[u];
                if (c < th) {
                    float nk[KNN];
                    nk[0] = fminf(kb[0], c);
#pragma unroll
                    for (int s = 1; s < KNN; s++) nk[s] = fminf(kb[s], fmaxf(kb[s - 1], c));
#pragma unroll
                    for (int s = 0; s < KNN; s++) kb[s] = nk[s];
                    th = kb[KNN - 1];
                }
            }
        }
    }

    // ---- Merge 4 quarter lists -> global 10 smallest; thresh = kb[9].
    if (qt) {
#pragma unroll
        for (int s = 0; s < KNN; s++) fbuf[((qt - 1) * 256 + q) * KNN + s] = kb[s];
    }
    __syncthreads();
    if (!qt) {
#pragma unroll
        for (int L = 0; L < 3; L++) {
#pragma unroll
            for (int s = 0; s < KNN; s++) {
                float c = fbuf[(L * 256 + q) * KNN + s];
                float nk[KNN];
                nk[0] = fminf(kb[0], c);
#pragma unroll
                for (int t2 = 1; t2 < KNN; t2++) nk[t2] = fminf(kb[t2], fmaxf(kb[t2 - 1], c));
#pragma unroll
                for (int t2 = 0; t2 < KNN; t2++) kb[t2] = nk[t2];
            }
        }
        sthr[q] = kb[KNN - 1];
    }
    __syncthreads();
    const float thresh = sthr[q];

    // ---- Pass 2 (per quarter): first-10-by-index with key <= thresh
    // (keys recomputed bit-identically; quarter-ordered concat == global
    //  ascending index order == top_k tie-break).
    int myidx[KNN];
#pragma unroll
    for (int i = 0; i < KNN; i++) myidx[i] = 0;
    int cnt = 0;

    for (int m0 = mlo; m0 < mhi; m0 += 8) {
        float key[8];
#pragma unroll
        for (int up = 0; up < 4; up++)
            keys2(pxy[(m0 >> 1) + up], pzw[(m0 >> 1) + up],
                  xn2, yn2, zn2, sqn2, neg2, eps2, key[2 * up], key[2 * up + 1]);
        float s0 = fminf(fminf((key[0] >= 0.1f) ? key[0] : FINF, (key[1] >= 0.1f) ? key[1] : FINF),
                         fminf((key[2] >= 0.1f) ? key[2] : FINF, (key[3] >= 0.1f) ? key[3] : FINF));
        float s1 = fminf(fminf((key[4] >= 0.1f) ? key[4] : FINF, (key[5] >= 0.1f) ? key[5] : FINF),
                         fminf((key[6] >= 0.1f) ? key[6] : FINF, (key[7] >= 0.1f) ? key[7] : FINF));
        if (fminf(s0, s1) <= thresh) {
#pragma unroll
            for (int u = 0; u < 8; u++) {
                float c = key[u];
                if (c <= thresh && c >= 0.1f && cnt < KNN) {
                    myidx[cnt] = m0 + u;
                    cnt++;
                }
            }
        }
    }

    const int base = (b * NPTS + n) * 4 + qt;
    g_qcnt[base] = cnt;
#pragma unroll
    for (int s = 0; s < KNN; s++) g_qidx[base * KNN + s] = myidx[s];
}

// loss: gather neighbors, 45 triangles, 10-smallest, mean sqrt; block min.
__global__ __launch_bounds__(256) void loss_kernel() {
    const int b     = blockIdx.x >> 3;
    const int chunk = blockIdx.x & 7;
    const int tid   = threadIdx.x;
    const int n     = chunk * 256 + tid;
    const int gq    = b * NPTS + n;
    const float FINF = __int_as_float(0x7f800000);

    // Build final index set: first 10 of quarter-ordered concat.
    int ib[KNN];
    int cnt = 0;
#pragma unroll
    for (int qt = 0; qt < 4; qt++) {
        const int c = g_qcnt[gq * 4 + qt];
#pragma unroll
        for (int s = 0; s < KNN; s++) {
            if (s < c && cnt < KNN) {
                ib[cnt] = g_qidx[(gq * 4 + qt) * KNN + s];
                cnt++;
            }
        }
    }

    const float4* s4b = g_s4 + b * NPTS;
    const float4* t4b = g_t4 + b * NPTS;
    float nsx[KNN], nsy[KNN], nsz[KNN], ntx[KNN], nty[KNN], ntz[KNN];
#pragma unroll
    for (int i = 0; i < KNN; i++) {
        float4 cs = s4b[ib[i]];
        float4 ct = t4b[ib[i]];
        nsx[i] = cs.x; nsy[i] = cs.y; nsz[i] = cs.z;
        ntx[i] = ct.x; nty[i] = ct.y; ntz[i] = ct.z;
    }
    const float4 pn = s4b[n];
    const float4 tn = t4b[n];
    const float xn = pn.x, yn = pn.y, zn = pn.z;
    const float xtn = tn.x, ytn = tn.y, ztn = tn.z;

    float ds0[KNN], dt0[KNN];
#pragma unroll
    for (int i = 0; i < KNN; i++) {
        float dx = xn - nsx[i], dy = yn - nsy[i], dz = zn - nsz[i];
        ds0[i] = dx * dx + dy * dy + dz * dz;
        float ex = xtn - ntx[i], ey = ytn - nty[i], ez = ztn - ntz[i];
        dt0[i] = ex * ex + ey * ey + ez * ez;
    }

    float lb[KNN];
#pragma unroll
    for (int i = 0; i < KNN; i++) lb[i] = FINF;

#pragma unroll
    for (int i = 0; i < KNN; i++) {
#pragma unroll
        for (int j = i + 1; j < KNN; j++) {
            float dx = nsx[i] - nsx[j], dy = nsy[i] - nsy[j], dz = nsz[i] - nsz[j];
            float bs = dx * dx + dy * dy + dz * dz;
            float l0 = ds0[i], l1 = bs, l2 = ds0[j];
            sort3(l0, l1, l2);

            float ex = ntx[i] - ntx[j], ey = nty[i] - nty[j], ez = ntz[i] - ntz[j];
            float bt = ex * ex + ey * ey + ez * ez;
            float m0 = dt0[i], m1 = bt, m2 = dt0[j];
            sort3(m0, m1, m2);
            m0 += 1e-6f; m1 += 1e-6f; m2 += 1e-6f;   // length_tgt = sort(tri) + EPS

            float e0 = l0 - m0, e1 = l1 - m1, e2 = l2 - m2;
            float num = e0 * e0 + e1 * e1 + e2 * e2;
            float s0 = l0 + m0, s1 = l1 + m1, s2 = l2 + m2;
            float den = s0 * s0 + s1 * s1 + s2 * s2;
            float ck = num / den;

            float nl[KNN];
            nl[0] = fminf(lb[0], ck);
#pragma unroll
            for (int s = 1; s < KNN; s++) nl[s] = fminf(lb[s], fmaxf(lb[s - 1], ck));
#pragma unroll
            for (int s = 0; s < KNN; s++) lb[s] = nl[s];
        }
    }

    float acc = 0.0f;
#pragma unroll
    for (int i = 0; i < KNN; i++) acc += sqrtf(lb[i] + 1e-6f);   // ascending order
    const float mloss = acc / 10.0f;
    g_loss[gq] = mloss;

    // Block min -> atomicMin on float bits (all values > 0)
    float v = mloss;
#pragma unroll
    for (int o = 16; o > 0; o >>= 1) v = fminf(v, __shfl_xor_sync(0xffffffffu, v, o));
    __shared__ float wmin[8];
    if ((tid & 31) == 0) wmin[tid >> 5] = v;
    __syncthreads();
    if (tid == 0) {
        float bm = wmin[0];
#pragma unroll
        for (int w = 1; w < 8; w++) bm = fminf(bm, wmin[w]);
        atomicMin(&g_min[b], (unsigned int)__float_as_int(bm));
    }
}

__global__ __launch_bounds__(256) void weight_kernel(float* __restrict__ out) {
    const int b = blockIdx.x >> 3;
    const int i = (blockIdx.x & 7) * 256 + threadIdx.x;
    const float minl = __int_as_float((int)g_min[b]);
    float t = g_loss[b * NPTS + i] - minl;
    float w = 2.0f / (1.0f + expf(30.0f * t));   // 2*sigmoid(-30*t)
    out[b * NPTS + i] = (w > 0.6f) ? 1.0f : 0.0f;
}

extern "C" void kernel_launch(void* const* d_in, const int* in_sizes, int n_in,
                              void* d_out, int out_size) {
    const float* src = (const float*)d_in[0];
    const float* tgt = (const float*)d_in[1];
    float* out = (float*)d_out;

    cudaFuncSetAttribute(knn_kernel, cudaFuncAttributeMaxDynamicSharedMemorySize, SM_TOTAL);

    prep_kernel<<<BATCH * 8, 256>>>(src, tgt);
    knn_kernel<<<BATCH * 8, 1024, SM_TOTAL>>>();
    loss_kernel<<<BATCH * 8, 256>>>();
    weight_kernel<<<BATCH * 8, 256>>>(out);
}

// round 16
// speedup vs baseline: 1.2476x; 1.2476x over previous
#include <cuda_runtime.h>
#include <math.h>

#define BATCH 16
#define NPTS  2048
#define KNN   10

__device__ float g_loss[BATCH * NPTS];
__device__ float g_blockmin[BATCH * 8];   // plain stores each run; no init needed

// Packed f32x2 helpers (per-lane IEEE fp32, identical rounding to scalar ops)
#define PACK2(out, lo, hi)  asm("mov.b64 %0, {%1, %2};" : "=l"(out) : "f"(lo), "f"(hi))
#define UNPACK2(lo, hi, in) asm("mov.b64 {%0, %1}, %2;" : "=f"(lo), "=f"(hi) : "l"(in))
#define MUL2(out, a, b)     asm("mul.rn.f32x2 %0, %1, %2;" : "=l"(out) : "l"(a), "l"(b))
#define ADD2(out, a, b)     asm("add.rn.f32x2 %0, %1, %2;" : "=l"(out) : "l"(a), "l"(b))
#define FMA2(out, a, b, c)  asm("fma.rn.f32x2 %0, %1, %2, %3;" : "=l"(out) : "l"(a), "l"(b), "l"(c))

typedef unsigned long long u64;

__device__ __forceinline__ void sort3(float& a, float& b, float& c) {
    float lo = fminf(a, b), hi = fmaxf(a, b);
    float l0 = fminf(lo, c);
    float l2 = fmaxf(hi, c);
    float l1 = fmaxf(lo, fminf(hi, c));
    a = l0; b = l1; c = l2;
}

// keys for candidate pair (2u, 2u+1): key = ((sqn + sq_m) - 2*dot) + 1e-7,
// dot = x*cx fma y*cy fma z*cz — identical rounding to the verified scalar.
__device__ __forceinline__ void keys2(const float4 xy, const float4 zw,
                                      u64 xn2, u64 yn2, u64 zn2, u64 sqn2,
                                      u64 neg2, u64 eps2,
                                      float& k0, float& k1) {
    u64 cx2, cy2, cz2, cw2, t, s, d, k;
    PACK2(cx2, xy.x, xy.y); PACK2(cy2, xy.z, xy.w);
    PACK2(cz2, zw.x, zw.y); PACK2(cw2, zw.z, zw.w);
    MUL2(t, xn2, cx2);
    FMA2(t, yn2, cy2, t);
    FMA2(t, zn2, cz2, t);          // dot
    ADD2(s, sqn2, cw2);            // sqn + sq_m
    FMA2(d, t, neg2, s);           // d2 = s - 2*dot (one rounding, == scalar)
    ADD2(k, d, eps2);              // key = d2 + 1e-7
    UNPACK2(k0, k1, k);
}

// Dynamic smem layout (64 KB total) — same as the measured-best round-9 kernel
#define SM_PXY   0                       // 1024 float4  (16 KB)
#define SM_PZW   16384                   // 1024 float4  (16 KB)
#define SM_FBUF  32768                   // 256*10 float (10 KB)  merge buffer
#define SM_IBUF0 43008                   // 256*10 int   (10 KB)
#define SM_IBUF1 53248                   // 256*10 int   (10 KB)
#define SM_THR   63488                   // 256 float    (1 KB)
#define SM_CNT   64512                   // 256 int      (1 KB)
#define SM_TOTAL 65536

__global__ __launch_bounds__(512) void knn_loss_kernel(const float* __restrict__ src,
                                                       const float* __restrict__ tgt) {
    extern __shared__ unsigned char smem[];
    float4* pxy  = (float4*)(smem + SM_PXY);   // (x0,x1,y0,y1) per candidate pair
    float4* pzw  = (float4*)(smem + SM_PZW);   // (z0,z1,sq0,sq1)
    float*  fbuf = (float*)(smem + SM_FBUF);
    int*    ibf0 = (int*)(smem + SM_IBUF0);
    int*    ibf1 = (int*)(smem + SM_IBUF1);
    float*  sthr = (float*)(smem + SM_THR);
    int*    scnt = (int*)(smem + SM_CNT);
    __shared__ float wmin[16];

    const int b     = blockIdx.x >> 3;
    const int chunk = blockIdx.x & 7;
    const int tid   = threadIdx.x;
    const int q     = tid & 255;          // query slot within chunk
    const int half  = tid >> 8;           // 0: candidates [0,1024), 1: [1024,2048)
    const int n     = chunk * 256 + q;

    // ---- Fused prep: load src pairs straight from global, compute |p|^2.
    const float* sb = src + b * 3 * NPTS;
    const float* tb = tgt + b * 3 * NPTS;
    for (int i = tid; i < NPTS / 2; i += 512) {
        float2 xx = ((const float2*)sb)[i];
        float2 yy = ((const float2*)(sb + NPTS))[i];
        float2 zz = ((const float2*)(sb + 2 * NPTS))[i];
        float q0 = xx.x * xx.x + yy.x * yy.x + zz.x * zz.x;   // same expr as verified prep
        float q1 = xx.y * xx.y + yy.y * yy.y + zz.y * zz.y;
        pxy[i] = make_float4(xx.x, xx.y, yy.x, yy.y);
        pzw[i] = make_float4(zz.x, zz.y, q0, q1);
    }
    __syncthreads();

    const float FINF = __int_as_float(0x7f800000);

    // Own point from smem pair (parity select)
    const float4 pa = pxy[n >> 1];
    const float4 pc = pzw[n >> 1];
    const int par = n & 1;
    const float xn  = par ? pa.y : pa.x;
    const float yn  = par ? pa.w : pa.z;
    const float zn  = par ? pc.y : pc.x;
    const float sqn = par ? pc.w : pc.z;

    u64 xn2, yn2, zn2, sqn2, neg2, eps2;
    PACK2(xn2, xn, xn); PACK2(yn2, yn, yn);
    PACK2(zn2, zn, zn); PACK2(sqn2, sqn, sqn);
    { float m2 = -2.0f, ep = 1e-7f; PACK2(neg2, m2, m2); PACK2(eps2, ep, ep); }

    const int mlo = half * (NPTS / 2);
    const int mhi = mlo + NPTS / 2;

    // ---- Pass 1 (per half): 10 smallest key VALUES (mask key >= 0.1),
    // min-max lattice insert; kb sorted ascending, slots independent.
    float kb[KNN];
#pragma unroll
    for (int i = 0; i < KNN; i++) kb[i] = FINF;
    float th = FINF;

    for (int m0 = mlo; m0 < mhi; m0 += 8) {
        float key[8];
#pragma unroll
        for (int up = 0; up < 4; up++)
            keys2(pxy[(m0 >> 1) + up], pzw[(m0 >> 1) + up],
                  xn2, yn2, zn2, sqn2, neg2, eps2, key[2 * up], key[2 * up + 1]);
#pragma unroll
        for (int u = 0; u < 8; u++) {
            float c = key[u];
            if (c < th && c >= 0.1f) {
                float nk[KNN];
                nk[0] = fminf(kb[0], c);
#pragma unroll
                for (int s = 1; s < KNN; s++) nk[s] = fminf(kb[s], fmaxf(kb[s - 1], c));
#pragma unroll
                for (int s = 0; s < KNN; s++) kb[s] = nk[s];
                th = kb[KNN - 1];
            }
        }
    }

    // ---- Merge the two halves' value lists: final 10 smallest of union.
    if (half) {
#pragma unroll
        for (int s = 0; s < KNN; s++) fbuf[q * KNN + s] = kb[s];
    }
    __syncthreads();
    if (!half) {
#pragma unroll
        for (int s = 0; s < KNN; s++) {
            float c = fbuf[q * KNN + s];
            float nk[KNN];
            nk[0] = fminf(kb[0], c);
#pragma unroll
            for (int t2 = 1; t2 < KNN; t2++) nk[t2] = fminf(kb[t2], fmaxf(kb[t2 - 1], c));
#pragma unroll
            for (int t2 = 0; t2 < KNN; t2++) kb[t2] = nk[t2];
        }
        sthr[q] = kb[KNN - 1];   // 10th smallest value overall
    }
    __syncthreads();
    const float thresh = sthr[q];

    // ---- Pass 2 (per half): collect first-10-by-index with key <= thresh
    // (keys recomputed bit-identically; half0 indices all < half1 indices,
    //  so concatenation == global ascending order == top_k tie-break).
    int myidx[KNN];
#pragma unroll
    for (int i = 0; i < KNN; i++) myidx[i] = 0;
    int cnt = 0;

    for (int m0 = mlo; m0 < mhi; m0 += 8) {
        float key[8];
#pragma unroll
        for (int up = 0; up < 4; up++)
            keys2(pxy[(m0 >> 1) + up], pzw[(m0 >> 1) + up],
                  xn2, yn2, zn2, sqn2, neg2, eps2, key[2 * up], key[2 * up + 1]);
#pragma unroll
        for (int u = 0; u < 8; u++) {
            float c = key[u];
            if (c <= thresh && c >= 0.1f && cnt < KNN) {
                myidx[cnt] = m0 + u;
                cnt++;
            }
        }
    }

    {
        int* dst = half ? ibf1 : ibf0;
#pragma unroll
        for (int s = 0; s < KNN; s++) dst[q * KNN + s] = myidx[s];
        if (!half) scnt[q] = cnt;
    }
    __syncthreads();

    // Both halves build the final index set (first 10 of concat).
    int ib[KNN];
    {
        const int c0 = scnt[q];
#pragma unroll
        for (int s = 0; s < KNN; s++)
            ib[s] = (s < c0) ? ibf0[q * KNN + s] : ibf1[q * KNN + (s - c0)];
    }

    // ---- Phase 2: gather 10 neighbors — src from smem pairs, tgt from global.
    float nsx[KNN], nsy[KNN], nsz[KNN], ntx[KNN], nty[KNN], ntz[KNN];
#pragma unroll
    for (int i = 0; i < KNN; i++) {
        const int m = ib[i];
        const float4 ca = pxy[m >> 1];
        const float4 cc = pzw[m >> 1];
        const int mp = m & 1;
        nsx[i] = mp ? ca.y : ca.x;
        nsy[i] = mp ? ca.w : ca.z;
        nsz[i] = mp ? cc.y : cc.x;
        ntx[i] = tb[m];
        nty[i] = tb[NPTS + m];
        ntz[i] = tb[2 * NPTS + m];
    }
    const float xtn = tb[n], ytn = tb[NPTS + n], ztn = tb[2 * NPTS + n];

    float ds0[KNN], dt0[KNN];
#pragma unroll
    for (int i = 0; i < KNN; i++) {
        float dx = xn - nsx[i], dy = yn - nsy[i], dz = zn - nsz[i];
        ds0[i] = dx * dx + dy * dy + dz * dz;
        float ex = xtn - ntx[i], ey = ytn - nty[i], ez = ztn - ntz[i];
        dt0[i] = ex * ex + ey * ey + ez * ez;
    }

    // ---- Phase 3: 45 pairs split 23/22 across the halves; 10-smallest via
    // lattice (kept sorted ascending). Loss multiset -> split is result-exact.
    float lb[KNN];
#pragma unroll
    for (int i = 0; i < KNN; i++) lb[i] = FINF;

    int p = 0;
#pragma unroll
    for (int i = 0; i < KNN; i++) {
#pragma unroll
        for (int j = i + 1; j < KNN; j++) {
            if ((half == 0) ? (p < 23) : (p >= 23)) {
                float dx = nsx[i] - nsx[j], dy = nsy[i] - nsy[j], dz = nsz[i] - nsz[j];
                float bs = dx * dx + dy * dy + dz * dz;
                float l0 = ds0[i], l1 = bs, l2 = ds0[j];
                sort3(l0, l1, l2);

                float ex = ntx[i] - ntx[j], ey = nty[i] - nty[j], ez = ntz[i] - ntz[j];
                float bt = ex * ex + ey * ey + ez * ez;
                float m0 = dt0[i], m1 = bt, m2 = dt0[j];
                sort3(m0, m1, m2);
                m0 += 1e-6f; m1 += 1e-6f; m2 += 1e-6f;   // length_tgt + EPS

                float e0 = l0 - m0, e1 = l1 - m1, e2 = l2 - m2;
                float num = e0 * e0 + e1 * e1 + e2 * e2;
                float s0 = l0 + m0, s1 = l1 + m1, s2 = l2 + m2;
                float den = s0 * s0 + s1 * s1 + s2 * s2;
                float ck = num / den;

                float nl[KNN];
                nl[0] = fminf(lb[0], ck);
#pragma unroll
                for (int s = 1; s < KNN; s++) nl[s] = fminf(lb[s], fmaxf(lb[s - 1], ck));
#pragma unroll
                for (int s = 0; s < KNN; s++) lb[s] = nl[s];
            }
            p++;
        }
    }

    if (half) {
#pragma unroll
        for (int s = 0; s < KNN; s++) fbuf[q * KNN + s] = lb[s];
    }
    __syncthreads();

    float mloss = 0.0f;
    if (!half) {
#pragma unroll
        for (int s = 0; s < KNN; s++) {
            float c = fbuf[q * KNN + s];
            float nl[KNN];
            nl[0] = fminf(lb[0], c);
#pragma unroll
            for (int t2 = 1; t2 < KNN; t2++) nl[t2] = fminf(lb[t2], fmaxf(lb[t2 - 1], c));
#pragma unroll
            for (int t2 = 0; t2 < KNN; t2++) lb[t2] = nl[t2];
        }
        float acc = 0.0f;
#pragma unroll
        for (int i = 0; i < KNN; i++) acc += sqrtf(lb[i] + 1e-6f);   // ascending order
        mloss = acc / 10.0f;
        g_loss[b * NPTS + n] = mloss;
    }

    // ---- Block min -> plain store (no atomics, no init kernel needed)
    float v = (!half) ? mloss : FINF;
#pragma unroll
    for (int o = 16; o > 0; o >>= 1) v = fminf(v, __shfl_xor_sync(0xffffffffu, v, o));
    if ((tid & 31) == 0) wmin[tid >> 5] = v;
    __syncthreads();
    if (tid == 0) {
        float bm = wmin[0];
#pragma unroll
        for (int w = 1; w < 16; w++) bm = fminf(bm, wmin[w]);
        g_blockmin[blockIdx.x] = bm;
    }
}

__global__ __launch_bounds__(256) void weight_kernel(float* __restrict__ out) {
    const int b = blockIdx.x >> 3;
    const int i = (blockIdx.x & 7) * 256 + threadIdx.x;
    float minl = g_blockmin[b * 8];
#pragma unroll
    for (int j = 1; j < 8; j++) minl = fminf(minl, g_blockmin[b * 8 + j]);
    float t = g_loss[b * NPTS + i] - minl;
    float w = 2.0f / (1.0f + expf(30.0f * t));   // 2*sigmoid(-30*t)
    out[b * NPTS + i] = (w > 0.6f) ? 1.0f : 0.0f;
}

extern "C" void kernel_launch(void* const* d_in, const int* in_sizes, int n_in,
                              void* d_out, int out_size) {
    const float* src = (const float*)d_in[0];
    const float* tgt = (const float*)d_in[1];
    float* out = (float*)d_out;

    cudaFuncSetAttribute(knn_loss_kernel, cudaFuncAttributeMaxDynamicSharedMemorySize, SM_TOTAL);

    knn_loss_kernel<<<BATCH * 8, 512, SM_TOTAL>>>(src, tgt);
    weight_kernel<<<BATCH * 8, 256>>>(out);
}